// round 1
// baseline (speedup 1.0000x reference)
#include <cuda_runtime.h>
#include <cstdint>

// Problem constants (match reference_code)
#define NLINKS   10000
#define NPATHS   100000
#define PLEN     8
#define HDIM     32
#define RDIM     8
#define TROUNDS  8
#define EDGES    (NPATHS * PLEN)

typedef unsigned long long ULL;

// ---------------- scratch (no cudaMalloc allowed) ----------------
__device__ float g_link_state[NLINKS * HDIM];          // 1.28 MB
__device__ float g_path_state[NPATHS * HDIM];          // 12.8 MB
__device__ float g_hs[(size_t)EDGES * HDIM];           // 102.4 MB, link-sorted hop hiddens
__device__ int   g_lk[EDGES];                          // link id per slot t = 8p+s
__device__ int   g_pos[EDGES];                         // sorted position per slot t
__device__ int   g_hist[NLINKS];
__device__ int   g_off[NLINKS + 1];
__device__ int   g_cur[NLINKS];

// ---------------- helpers ----------------
__device__ __forceinline__ ULL fma2(ULL a, ULL b, ULL c) {
    ULL d;
    asm("fma.rn.f32x2 %0, %1, %2, %3;" : "=l"(d) : "l"(a), "l"(b), "l"(c));
    return d;
}
__device__ __forceinline__ float f2lo(ULL v) { return __uint_as_float((unsigned)(v & 0xffffffffULL)); }
__device__ __forceinline__ float f2hi(ULL v) { return __uint_as_float((unsigned)(v >> 32)); }
__device__ __forceinline__ float hsum2(ULL v) { return f2lo(v) + f2hi(v); }

__device__ __forceinline__ float sigmoid_f(float x) {
    return __fdividef(1.f, 1.f + __expf(-x));
}
__device__ __forceinline__ float tanh_f(float x) {
    float e = __expf(2.f * x);
    return 1.f - __fdividef(2.f, e + 1.f);
}

// ---------------- setup kernels ----------------
__global__ void k_init(const float* __restrict__ cap, const float* __restrict__ bw) {
    int i = blockIdx.x * blockDim.x + threadIdx.x;
    if (i < NPATHS * HDIM) g_path_state[i] = ((i & (HDIM - 1)) == 0) ? bw[i / HDIM] : 0.f;
    if (i < NLINKS * HDIM) g_link_state[i] = ((i & (HDIM - 1)) == 0) ? cap[i / HDIM] : 0.f;
    if (i < NLINKS) g_hist[i] = 0;
}

__global__ void k_map(const int* __restrict__ paths, const int* __restrict__ seqs,
                      const int* __restrict__ links) {
    int e = blockIdx.x * blockDim.x + threadIdx.x;
    if (e < EDGES) g_lk[paths[e] * PLEN + seqs[e]] = links[e];
}

__global__ void k_hist() {
    int t = blockIdx.x * blockDim.x + threadIdx.x;
    if (t < EDGES) atomicAdd(&g_hist[g_lk[t]], 1);
}

__global__ void k_scan() {
    __shared__ int part[1024];
    int tid = threadIdx.x;
    const int CH = (NLINKS + 1023) / 1024;  // 10
    int base = tid * CH;
    int s = 0;
    for (int i = 0; i < CH; i++) {
        int idx = base + i;
        if (idx < NLINKS) s += g_hist[idx];
    }
    part[tid] = s;
    __syncthreads();
    for (int off = 1; off < 1024; off <<= 1) {
        int add = (tid >= off) ? part[tid - off] : 0;
        __syncthreads();
        part[tid] += add;
        __syncthreads();
    }
    int run = (tid == 0) ? 0 : part[tid - 1];
    for (int i = 0; i < CH; i++) {
        int idx = base + i;
        if (idx < NLINKS) {
            g_off[idx] = run;
            g_cur[idx] = run;
            run += g_hist[idx];
        }
    }
    if (tid == 1023) g_off[NLINKS] = part[1023];
}

__global__ void k_pos() {
    int t = blockIdx.x * blockDim.x + threadIdx.x;
    if (t < EDGES) g_pos[t] = atomicAdd(&g_cur[g_lk[t]], 1);
}

// ---------------- path GRU (dominant kernel) ----------------
// thread-per-path; weights broadcast from shared as LDS.128; math in fma.rn.f32x2
__global__ __launch_bounds__(128, 4) void k_path(
    const float* __restrict__ pWih, const float* __restrict__ pWhh,
    const float* __restrict__ pbih, const float* __restrict__ pbhh) {
    __shared__ float sWih[3 * HDIM * HDIM];
    __shared__ float sWhh[3 * HDIM * HDIM];
    __shared__ float sb[6 * HDIM];  // bih[96] then bhh[96]

    for (int i = threadIdx.x; i < 3 * HDIM * HDIM; i += 128) {
        sWih[i] = pWih[i];
        sWhh[i] = pWhh[i];
    }
    for (int i = threadIdx.x; i < 3 * HDIM; i += 128) {
        sb[i] = pbih[i];
        sb[3 * HDIM + i] = pbhh[i];
    }
    __syncthreads();

    int p = blockIdx.x * 128 + threadIdx.x;
    if (p >= NPATHS) return;

    // current hidden, pair-packed
    ULL h2[16];
    {
        const ulonglong2* src = (const ulonglong2*)&g_path_state[p * HDIM];
#pragma unroll
        for (int i = 0; i < 8; i++) {
            ulonglong2 v = src[i];
            h2[2 * i] = v.x;
            h2[2 * i + 1] = v.y;
        }
    }
    const float* hrow_prev = &g_path_state[p * HDIM];

#pragma unroll 1
    for (int s = 0; s < PLEN; s++) {
        int t = p * PLEN + s;
        int lk = g_lk[t];
        int pos = g_pos[t];
        float* hrow_new = &g_hs[(size_t)pos * HDIM];

        ULL x2[16];
        {
            const ulonglong2* src = (const ulonglong2*)&g_link_state[lk * HDIM];
#pragma unroll
            for (int i = 0; i < 8; i++) {
                ulonglong2 v = src[i];
                x2[2 * i] = v.x;
                x2[2 * i + 1] = v.y;
            }
        }

#pragma unroll 1
        for (int j4 = 0; j4 < 8; j4++) {
            float4 hp4 = *(const float4*)(hrow_prev + j4 * 4);
            float hn[4];
#pragma unroll
            for (int u = 0; u < 4; u++) {
                int jj = j4 * 4 + u;
                ULL air = 0, aiz = 0, ain = 0, ahr = 0, ahz = 0, ahn = 0;
                const ulonglong2* wir = (const ulonglong2*)&sWih[jj * HDIM];
                const ulonglong2* wiz = (const ulonglong2*)&sWih[(HDIM + jj) * HDIM];
                const ulonglong2* win = (const ulonglong2*)&sWih[(2 * HDIM + jj) * HDIM];
                const ulonglong2* whr = (const ulonglong2*)&sWhh[jj * HDIM];
                const ulonglong2* whz = (const ulonglong2*)&sWhh[(HDIM + jj) * HDIM];
                const ulonglong2* whn = (const ulonglong2*)&sWhh[(2 * HDIM + jj) * HDIM];
#pragma unroll
                for (int q = 0; q < 8; q++) {
                    ulonglong2 w;
                    w = wir[q]; air = fma2(x2[2 * q], w.x, air); air = fma2(x2[2 * q + 1], w.y, air);
                    w = wiz[q]; aiz = fma2(x2[2 * q], w.x, aiz); aiz = fma2(x2[2 * q + 1], w.y, aiz);
                    w = win[q]; ain = fma2(x2[2 * q], w.x, ain); ain = fma2(x2[2 * q + 1], w.y, ain);
                    w = whr[q]; ahr = fma2(h2[2 * q], w.x, ahr); ahr = fma2(h2[2 * q + 1], w.y, ahr);
                    w = whz[q]; ahz = fma2(h2[2 * q], w.x, ahz); ahz = fma2(h2[2 * q + 1], w.y, ahz);
                    w = whn[q]; ahn = fma2(h2[2 * q], w.x, ahn); ahn = fma2(h2[2 * q + 1], w.y, ahn);
                }
                float vr = hsum2(air) + sb[jj] + hsum2(ahr) + sb[96 + jj];
                float vz = hsum2(aiz) + sb[32 + jj] + hsum2(ahz) + sb[128 + jj];
                float gin = hsum2(ain) + sb[64 + jj];
                float ghn = hsum2(ahn) + sb[160 + jj];
                float r = sigmoid_f(vr);
                float z = sigmoid_f(vz);
                float nv = tanh_f(gin + r * ghn);
                float hp = (u == 0) ? hp4.x : (u == 1) ? hp4.y : (u == 2) ? hp4.z : hp4.w;
                hn[u] = (1.f - z) * nv + z * hp;
            }
            *(float4*)(hrow_new + j4 * 4) = make_float4(hn[0], hn[1], hn[2], hn[3]);
        }
        // reload the just-written row as the next step's hidden (same-thread RAW)
        {
            const ulonglong2* src = (const ulonglong2*)hrow_new;
#pragma unroll
            for (int i = 0; i < 8; i++) {
                ulonglong2 v = src[i];
                h2[2 * i] = v.x;
                h2[2 * i + 1] = v.y;
            }
        }
        hrow_prev = hrow_new;
    }
    // final hidden -> path_state (carried to next round / readout)
    {
        ulonglong2* dst = (ulonglong2*)&g_path_state[p * HDIM];
#pragma unroll
        for (int i = 0; i < 8; i++) {
            ulonglong2 v;
            v.x = h2[2 * i];
            v.y = h2[2 * i + 1];
            dst[i] = v;
        }
    }
}

// ---------------- link aggregation + link GRU (warp per link, no atomics) ---
__global__ __launch_bounds__(256) void k_link(
    const float* __restrict__ lWih, const float* __restrict__ lWhh,
    const float* __restrict__ lbih, const float* __restrict__ lbhh) {
    __shared__ float sWihT[3 * HDIM * HDIM];  // transposed: [k][j]
    __shared__ float sWhhT[3 * HDIM * HDIM];
    __shared__ float sbi[3 * HDIM], sbh[3 * HDIM];

    for (int i = threadIdx.x; i < 3 * HDIM * HDIM; i += 256) {
        int j = i / HDIM, k = i % HDIM;
        sWihT[k * 96 + j] = lWih[i];
        sWhhT[k * 96 + j] = lWhh[i];
    }
    for (int i = threadIdx.x; i < 3 * HDIM; i += 256) {
        sbi[i] = lbih[i];
        sbh[i] = lbhh[i];
    }
    __syncthreads();

    int w = (blockIdx.x * 256 + threadIdx.x) >> 5;  // link id
    int lane = threadIdx.x & 31;
    if (w >= NLINKS) return;

    float x = 0.f;
    int b = g_off[w], e = g_off[w + 1];
    for (int i = b; i < e; i++) x += g_hs[(size_t)i * HDIM + lane];

    float h = g_link_state[w * HDIM + lane];

    float air = sbi[lane], aiz = sbi[32 + lane], ain = sbi[64 + lane];
    float ahr = sbh[lane], ahz = sbh[32 + lane], ahn = sbh[64 + lane];
#pragma unroll
    for (int k = 0; k < 32; k++) {
        float xv = __shfl_sync(0xffffffffu, x, k);
        float hv = __shfl_sync(0xffffffffu, h, k);
        air += xv * sWihT[k * 96 + lane];
        aiz += xv * sWihT[k * 96 + 32 + lane];
        ain += xv * sWihT[k * 96 + 64 + lane];
        ahr += hv * sWhhT[k * 96 + lane];
        ahz += hv * sWhhT[k * 96 + 32 + lane];
        ahn += hv * sWhhT[k * 96 + 64 + lane];
    }
    float r = sigmoid_f(air + ahr);
    float z = sigmoid_f(aiz + ahz);
    float nv = tanh_f(ain + r * ahn);
    g_link_state[w * HDIM + lane] = (1.f - z) * nv + z * h;
}

// ---------------- readout MLP ----------------
__global__ __launch_bounds__(256) void k_readout(
    const float* __restrict__ W1, const float* __restrict__ b1,
    const float* __restrict__ W2, const float* __restrict__ b2,
    const float* __restrict__ W3, const float* __restrict__ b3,
    float* __restrict__ out) {
    __shared__ float s1[RDIM * HDIM], sb1[RDIM], s2[RDIM * RDIM], sb2[RDIM], s3[RDIM], sb3;
    for (int i = threadIdx.x; i < RDIM * HDIM; i += 256) s1[i] = W1[i];
    if (threadIdx.x < RDIM * RDIM) s2[threadIdx.x] = W2[threadIdx.x];
    if (threadIdx.x < RDIM) {
        sb1[threadIdx.x] = b1[threadIdx.x];
        sb2[threadIdx.x] = b2[threadIdx.x];
        s3[threadIdx.x] = W3[threadIdx.x];
    }
    if (threadIdx.x == 0) sb3 = b3[0];
    __syncthreads();

    int p = blockIdx.x * 256 + threadIdx.x;
    if (p >= NPATHS) return;

    float x[HDIM];
    {
        const float4* src = (const float4*)&g_path_state[p * HDIM];
#pragma unroll
        for (int i = 0; i < 8; i++) {
            float4 v = src[i];
            x[4 * i] = v.x; x[4 * i + 1] = v.y; x[4 * i + 2] = v.z; x[4 * i + 3] = v.w;
        }
    }
    float y1[RDIM];
#pragma unroll
    for (int i = 0; i < RDIM; i++) {
        float d = sb1[i];
#pragma unroll
        for (int k = 0; k < HDIM; k++) d += x[k] * s1[i * HDIM + k];
        y1[i] = fmaxf(d, 0.f);
    }
    float y2[RDIM];
#pragma unroll
    for (int i = 0; i < RDIM; i++) {
        float d = sb2[i];
#pragma unroll
        for (int k = 0; k < RDIM; k++) d += y1[k] * s2[i * RDIM + k];
        y2[i] = fmaxf(d, 0.f);
    }
    float o = sb3;
#pragma unroll
    for (int k = 0; k < RDIM; k++) o += y2[k] * s3[k];
    out[p] = o;
}

// ---------------- launch ----------------
extern "C" void kernel_launch(void* const* d_in, const int* in_sizes, int n_in,
                              void* d_out, int out_size) {
    const int* links = (const int*)d_in[0];
    const int* paths = (const int*)d_in[1];
    const int* seqs  = (const int*)d_in[2];
    const float* cap = (const float*)d_in[3];
    const float* bw  = (const float*)d_in[4];
    const float* pWih = (const float*)d_in[5];
    const float* pWhh = (const float*)d_in[6];
    const float* pbih = (const float*)d_in[7];
    const float* pbhh = (const float*)d_in[8];
    const float* lWih = (const float*)d_in[9];
    const float* lWhh = (const float*)d_in[10];
    const float* lbih = (const float*)d_in[11];
    const float* lbhh = (const float*)d_in[12];
    const float* W1 = (const float*)d_in[13];
    const float* b1 = (const float*)d_in[14];
    const float* W2 = (const float*)d_in[15];
    const float* b2 = (const float*)d_in[16];
    const float* W3 = (const float*)d_in[17];
    const float* b3 = (const float*)d_in[18];
    float* out = (float*)d_out;

    (void)in_sizes; (void)n_in; (void)out_size;

    k_init<<<(NPATHS * HDIM + 255) / 256, 256>>>(cap, bw);
    k_map<<<(EDGES + 255) / 256, 256>>>(paths, seqs, links);
    k_hist<<<(EDGES + 255) / 256, 256>>>();
    k_scan<<<1, 1024>>>();
    k_pos<<<(EDGES + 255) / 256, 256>>>();

    for (int r = 0; r < TROUNDS; r++) {
        k_path<<<(NPATHS + 127) / 128, 128>>>(pWih, pWhh, pbih, pbhh);
        k_link<<<(NLINKS + 7) / 8, 256>>>(lWih, lWhh, lbih, lbhh);
    }
    k_readout<<<(NPATHS + 255) / 256, 256>>>(W1, b1, W2, b2, W3, b3, out);
}

// round 2
// speedup vs baseline: 1.3640x; 1.3640x over previous
#include <cuda_runtime.h>
#include <cstdint>

#define NLINKS   10000
#define NPATHS   100000
#define PLEN     8
#define HDIM     32
#define RDIM     8
#define TROUNDS  8
#define EDGES    (NPATHS * PLEN)

typedef unsigned long long ULL;

// ---------------- scratch (no cudaMalloc allowed) ----------------
__device__ float g_link_state[NLINKS * HDIM];
__device__ float g_path_state[NPATHS * HDIM];
__device__ float g_hs[(size_t)EDGES * HDIM];     // link-sorted hop hiddens
__device__ float g_gi[NLINKS * 96];              // per-link input-gate precompute
__device__ int   g_lk[EDGES];
__device__ int   g_pos[EDGES];
__device__ int   g_hist[NLINKS];
__device__ int   g_off[NLINKS + 1];
__device__ int   g_cur[NLINKS];

// ---------------- helpers ----------------
__device__ __forceinline__ ULL fma2(ULL a, ULL b, ULL c) {
    ULL d;
    asm("fma.rn.f32x2 %0, %1, %2, %3;" : "=l"(d) : "l"(a), "l"(b), "l"(c));
    return d;
}
__device__ __forceinline__ ULL mul2(ULL a, ULL b) {
    ULL d;
    asm("mul.rn.f32x2 %0, %1, %2;" : "=l"(d) : "l"(a), "l"(b));
    return d;
}
__device__ __forceinline__ ULL pk(float lo, float hi) {
    ULL r;
    asm("mov.b64 %0, {%1, %2};" : "=l"(r) : "f"(lo), "f"(hi));
    return r;
}
__device__ __forceinline__ float hsum2(ULL v) {
    float lo, hi;
    asm("mov.b64 {%0, %1}, %2;" : "=f"(lo), "=f"(hi) : "l"(v));
    return lo + hi;
}
__device__ __forceinline__ float sigmoid_f(float x) {
    return __fdividef(1.f, 1.f + __expf(-x));
}
__device__ __forceinline__ float tanh_f(float x) {
    float e = __expf(2.f * x);
    return 1.f - __fdividef(2.f, e + 1.f);
}

// ---------------- setup kernels ----------------
__global__ void k_init(const float* __restrict__ cap, const float* __restrict__ bw) {
    int i = blockIdx.x * blockDim.x + threadIdx.x;
    if (i < NPATHS * HDIM) g_path_state[i] = ((i & (HDIM - 1)) == 0) ? bw[i / HDIM] : 0.f;
    if (i < NLINKS * HDIM) g_link_state[i] = ((i & (HDIM - 1)) == 0) ? cap[i / HDIM] : 0.f;
    if (i < NLINKS) g_hist[i] = 0;
}

__global__ void k_map(const int* __restrict__ paths, const int* __restrict__ seqs,
                      const int* __restrict__ links) {
    int e = blockIdx.x * blockDim.x + threadIdx.x;
    if (e < EDGES) g_lk[paths[e] * PLEN + seqs[e]] = links[e];
}

__global__ void k_hist() {
    int t = blockIdx.x * blockDim.x + threadIdx.x;
    if (t < EDGES) atomicAdd(&g_hist[g_lk[t]], 1);
}

__global__ void k_scan() {
    __shared__ int part[1024];
    int tid = threadIdx.x;
    const int CH = (NLINKS + 1023) / 1024;
    int base = tid * CH;
    int s = 0;
    for (int i = 0; i < CH; i++) {
        int idx = base + i;
        if (idx < NLINKS) s += g_hist[idx];
    }
    part[tid] = s;
    __syncthreads();
    for (int off = 1; off < 1024; off <<= 1) {
        int add = (tid >= off) ? part[tid - off] : 0;
        __syncthreads();
        part[tid] += add;
        __syncthreads();
    }
    int run = (tid == 0) ? 0 : part[tid - 1];
    for (int i = 0; i < CH; i++) {
        int idx = base + i;
        if (idx < NLINKS) {
            g_off[idx] = run;
            g_cur[idx] = run;
            run += g_hist[idx];
        }
    }
    if (tid == 1023) g_off[NLINKS] = part[1023];
}

__global__ void k_pos() {
    int t = blockIdx.x * blockDim.x + threadIdx.x;
    if (t < EDGES) g_pos[t] = atomicAdd(&g_cur[g_lk[t]], 1);
}

// ---------------- per-round Gi precompute (per LINK, not per hop!) ---------
// Gi[link][j]      = link_state[link] . Wih_r[j] + bih_r[j] + bhh_r[j]
// Gi[link][32+j]   = ... gate z, bhh_z folded
// Gi[link][64+j]   = ... gate n, bih only (bhh_n stays inside r*(...))
__global__ __launch_bounds__(256) void k_gi(
    const float* __restrict__ pWih, const float* __restrict__ pbih,
    const float* __restrict__ pbhh) {
    __shared__ float sWT[HDIM * 96];  // [k][j]
    __shared__ float sb[96];
    for (int i = threadIdx.x; i < 96 * HDIM; i += 256) {
        int j = i / HDIM, k = i % HDIM;
        sWT[k * 96 + j] = pWih[i];
    }
    for (int i = threadIdx.x; i < 96; i += 256)
        sb[i] = pbih[i] + (i < 64 ? pbhh[i] : 0.f);
    __syncthreads();

    int w = (blockIdx.x * 256 + threadIdx.x) >> 5;
    int lane = threadIdx.x & 31;
    if (w >= NLINKS) return;

    float h = g_link_state[w * HDIM + lane];
    float a0 = sb[lane], a1 = sb[32 + lane], a2 = sb[64 + lane];
#pragma unroll
    for (int k = 0; k < 32; k++) {
        float hv = __shfl_sync(0xffffffffu, h, k);
        a0 += hv * sWT[k * 96 + lane];
        a1 += hv * sWT[k * 96 + 32 + lane];
        a2 += hv * sWT[k * 96 + 64 + lane];
    }
    g_gi[w * 96 + lane] = a0;
    g_gi[w * 96 + 32 + lane] = a1;
    g_gi[w * 96 + 64 + lane] = a2;
}

// ---------------- path GRU (dominant kernel) ----------------
// thread-per-path; only the h @ Whh^T half is computed here (gi gathered).
// h kept in registers (packed f32x2); per-thread smem slice (stride 36 floats,
// conflict-free for LDS.128) provides dynamically-indexed h for the blend.
__global__ __launch_bounds__(128, 4) void k_path(
    const float* __restrict__ pWhh, const float* __restrict__ pbhh) {
    __shared__ __align__(16) float sW[96 * HDIM];   // 12.3 KB
    __shared__ float sBn[HDIM];
    __shared__ __align__(16) float sH[128 * 36];    // 18.4 KB

    for (int i = threadIdx.x; i < 96 * HDIM; i += 128) sW[i] = pWhh[i];
    if (threadIdx.x < HDIM) sBn[threadIdx.x] = pbhh[64 + threadIdx.x];
    __syncthreads();

    int p = blockIdx.x * 128 + threadIdx.x;
    if (p >= NPATHS) return;
    float* myH = &sH[threadIdx.x * 36];

    ULL h2[16];
    {
        const ulonglong2* src = (const ulonglong2*)&g_path_state[p * HDIM];
#pragma unroll
        for (int i = 0; i < 8; i++) {
            ulonglong2 v = src[i];
            h2[2 * i] = v.x;
            h2[2 * i + 1] = v.y;
            ((ulonglong2*)myH)[i] = v;
        }
    }

    int lkn = g_lk[p * PLEN];
    int posn = g_pos[p * PLEN];

#pragma unroll 1
    for (int s = 0; s < PLEN; s++) {
        int lk = lkn, pos = posn;
        if (s + 1 < PLEN) {
            lkn = g_lk[p * PLEN + s + 1];
            posn = g_pos[p * PLEN + s + 1];
        }
        const float* gi = &g_gi[lk * 96];

#pragma unroll 1
        for (int j4 = 0; j4 < 8; j4++) {
            float4 gr = __ldg((const float4*)(gi + j4 * 4));
            float4 gz = __ldg((const float4*)(gi + 32 + j4 * 4));
            float4 gn = __ldg((const float4*)(gi + 64 + j4 * 4));
            ulonglong2 hb = ((const ulonglong2*)myH)[j4];

            float zz[4], nn[4];
#pragma unroll
            for (int u = 0; u < 4; u++) {
                int jj = j4 * 4 + u;
                ULL ar = 0, az = 0, an = 0;
                const ulonglong2* wr = (const ulonglong2*)&sW[jj * HDIM];
                const ulonglong2* wz = (const ulonglong2*)&sW[(32 + jj) * HDIM];
                const ulonglong2* wn = (const ulonglong2*)&sW[(64 + jj) * HDIM];
#pragma unroll
                for (int q = 0; q < 8; q++) {
                    ulonglong2 w;
                    w = wr[q]; ar = fma2(h2[2 * q], w.x, ar); ar = fma2(h2[2 * q + 1], w.y, ar);
                    w = wz[q]; az = fma2(h2[2 * q], w.x, az); az = fma2(h2[2 * q + 1], w.y, az);
                    w = wn[q]; an = fma2(h2[2 * q], w.x, an); an = fma2(h2[2 * q + 1], w.y, an);
                }
                float gir = (u == 0) ? gr.x : (u == 1) ? gr.y : (u == 2) ? gr.z : gr.w;
                float giz = (u == 0) ? gz.x : (u == 1) ? gz.y : (u == 2) ? gz.z : gz.w;
                float gin = (u == 0) ? gn.x : (u == 1) ? gn.y : (u == 2) ? gn.z : gn.w;
                float r = sigmoid_f(gir + hsum2(ar));
                float z = sigmoid_f(giz + hsum2(az));
                float nv = tanh_f(gin + r * (hsum2(an) + sBn[jj]));
                zz[u] = z;
                nn[u] = nv;
            }
            // packed blend: h_new = (1-z)*n + z*h_old
            ULL hn01 = fma2(pk(zz[0], zz[1]), hb.x,
                            mul2(pk(1.f - zz[0], 1.f - zz[1]), pk(nn[0], nn[1])));
            ULL hn23 = fma2(pk(zz[2], zz[3]), hb.y,
                            mul2(pk(1.f - zz[2], 1.f - zz[3]), pk(nn[2], nn[3])));
            ulonglong2 outv;
            outv.x = hn01;
            outv.y = hn23;
            ((ulonglong2*)myH)[j4] = outv;
        }

        // refresh packed regs from smem slice; emit row for link aggregation
        ulonglong2* dst = (ulonglong2*)&g_hs[(size_t)pos * HDIM];
#pragma unroll
        for (int i = 0; i < 8; i++) {
            ulonglong2 v = ((const ulonglong2*)myH)[i];
            h2[2 * i] = v.x;
            h2[2 * i + 1] = v.y;
            dst[i] = v;
        }
    }

    ulonglong2* dst = (ulonglong2*)&g_path_state[p * HDIM];
#pragma unroll
    for (int i = 0; i < 8; i++) {
        ulonglong2 v;
        v.x = h2[2 * i];
        v.y = h2[2 * i + 1];
        dst[i] = v;
    }
}

// ---------------- link aggregation + link GRU (warp per link) ----------------
__global__ __launch_bounds__(256) void k_link(
    const float* __restrict__ lWih, const float* __restrict__ lWhh,
    const float* __restrict__ lbih, const float* __restrict__ lbhh) {
    __shared__ float sWihT[3 * HDIM * HDIM];  // [k][j]
    __shared__ float sWhhT[3 * HDIM * HDIM];
    __shared__ float sbi[3 * HDIM], sbh[3 * HDIM];

    for (int i = threadIdx.x; i < 3 * HDIM * HDIM; i += 256) {
        int j = i / HDIM, k = i % HDIM;
        sWihT[k * 96 + j] = lWih[i];
        sWhhT[k * 96 + j] = lWhh[i];
    }
    for (int i = threadIdx.x; i < 3 * HDIM; i += 256) {
        sbi[i] = lbih[i];
        sbh[i] = lbhh[i];
    }
    __syncthreads();

    int w = (blockIdx.x * 256 + threadIdx.x) >> 5;
    int lane = threadIdx.x & 31;
    if (w >= NLINKS) return;

    int b = g_off[w], e = g_off[w + 1];
    float x0 = 0.f, x1 = 0.f, x2s = 0.f, x3 = 0.f;
    int i = b;
    for (; i + 4 <= e; i += 4) {
        x0 += g_hs[(size_t)(i + 0) * HDIM + lane];
        x1 += g_hs[(size_t)(i + 1) * HDIM + lane];
        x2s += g_hs[(size_t)(i + 2) * HDIM + lane];
        x3 += g_hs[(size_t)(i + 3) * HDIM + lane];
    }
    for (; i < e; i++) x0 += g_hs[(size_t)i * HDIM + lane];
    float x = (x0 + x1) + (x2s + x3);

    float h = g_link_state[w * HDIM + lane];

    float air = sbi[lane], aiz = sbi[32 + lane], ain = sbi[64 + lane];
    float ahr = sbh[lane], ahz = sbh[32 + lane], ahn = sbh[64 + lane];
#pragma unroll
    for (int k = 0; k < 32; k++) {
        float xv = __shfl_sync(0xffffffffu, x, k);
        float hv = __shfl_sync(0xffffffffu, h, k);
        air += xv * sWihT[k * 96 + lane];
        aiz += xv * sWihT[k * 96 + 32 + lane];
        ain += xv * sWihT[k * 96 + 64 + lane];
        ahr += hv * sWhhT[k * 96 + lane];
        ahz += hv * sWhhT[k * 96 + 32 + lane];
        ahn += hv * sWhhT[k * 96 + 64 + lane];
    }
    float r = sigmoid_f(air + ahr);
    float z = sigmoid_f(aiz + ahz);
    float nv = tanh_f(ain + r * ahn);
    g_link_state[w * HDIM + lane] = (1.f - z) * nv + z * h;
}

// ---------------- readout MLP ----------------
__global__ __launch_bounds__(256) void k_readout(
    const float* __restrict__ W1, const float* __restrict__ b1,
    const float* __restrict__ W2, const float* __restrict__ b2,
    const float* __restrict__ W3, const float* __restrict__ b3,
    float* __restrict__ out) {
    __shared__ float s1[RDIM * HDIM], sb1[RDIM], s2[RDIM * RDIM], sb2[RDIM], s3[RDIM], sb3;
    for (int i = threadIdx.x; i < RDIM * HDIM; i += 256) s1[i] = W1[i];
    if (threadIdx.x < RDIM * RDIM) s2[threadIdx.x] = W2[threadIdx.x];
    if (threadIdx.x < RDIM) {
        sb1[threadIdx.x] = b1[threadIdx.x];
        sb2[threadIdx.x] = b2[threadIdx.x];
        s3[threadIdx.x] = W3[threadIdx.x];
    }
    if (threadIdx.x == 0) sb3 = b3[0];
    __syncthreads();

    int p = blockIdx.x * 256 + threadIdx.x;
    if (p >= NPATHS) return;

    float x[HDIM];
    {
        const float4* src = (const float4*)&g_path_state[p * HDIM];
#pragma unroll
        for (int i = 0; i < 8; i++) {
            float4 v = src[i];
            x[4 * i] = v.x; x[4 * i + 1] = v.y; x[4 * i + 2] = v.z; x[4 * i + 3] = v.w;
        }
    }
    float y1[RDIM];
#pragma unroll
    for (int i = 0; i < RDIM; i++) {
        float d = sb1[i];
#pragma unroll
        for (int k = 0; k < HDIM; k++) d += x[k] * s1[i * HDIM + k];
        y1[i] = fmaxf(d, 0.f);
    }
    float y2[RDIM];
#pragma unroll
    for (int i = 0; i < RDIM; i++) {
        float d = sb2[i];
#pragma unroll
        for (int k = 0; k < RDIM; k++) d += y1[k] * s2[i * RDIM + k];
        y2[i] = fmaxf(d, 0.f);
    }
    float o = sb3;
#pragma unroll
    for (int k = 0; k < RDIM; k++) o += y2[k] * s3[k];
    out[p] = o;
}

// ---------------- launch ----------------
extern "C" void kernel_launch(void* const* d_in, const int* in_sizes, int n_in,
                              void* d_out, int out_size) {
    const int* links = (const int*)d_in[0];
    const int* paths = (const int*)d_in[1];
    const int* seqs  = (const int*)d_in[2];
    const float* cap = (const float*)d_in[3];
    const float* bw  = (const float*)d_in[4];
    const float* pWih = (const float*)d_in[5];
    const float* pWhh = (const float*)d_in[6];
    const float* pbih = (const float*)d_in[7];
    const float* pbhh = (const float*)d_in[8];
    const float* lWih = (const float*)d_in[9];
    const float* lWhh = (const float*)d_in[10];
    const float* lbih = (const float*)d_in[11];
    const float* lbhh = (const float*)d_in[12];
    const float* W1 = (const float*)d_in[13];
    const float* b1 = (const float*)d_in[14];
    const float* W2 = (const float*)d_in[15];
    const float* b2 = (const float*)d_in[16];
    const float* W3 = (const float*)d_in[17];
    const float* b3 = (const float*)d_in[18];
    float* out = (float*)d_out;

    (void)in_sizes; (void)n_in; (void)out_size;

    k_init<<<(NPATHS * HDIM + 255) / 256, 256>>>(cap, bw);
    k_map<<<(EDGES + 255) / 256, 256>>>(paths, seqs, links);
    k_hist<<<(EDGES + 255) / 256, 256>>>();
    k_scan<<<1, 1024>>>();
    k_pos<<<(EDGES + 255) / 256, 256>>>();

    for (int r = 0; r < TROUNDS; r++) {
        k_gi<<<(NLINKS * 32 + 255) / 256, 256>>>(pWih, pbih, pbhh);
        k_path<<<(NPATHS + 127) / 128, 128>>>(pWhh, pbhh);
        k_link<<<(NLINKS + 7) / 8, 256>>>(lWih, lWhh, lbih, lbhh);
    }
    k_readout<<<(NPATHS + 255) / 256, 256>>>(W1, b1, W2, b2, W3, b3, out);
}